// round 1
// baseline (speedup 1.0000x reference)
#include <cuda_runtime.h>
#include <cuda_bf16.h>
#include <mma.h>
#include <math.h>

using namespace nvcuda;

// ---------------- problem constants ----------------
#define BB    64      // batch
#define PP    196     // encoder positions
#define ENC   512
#define EE    1024    // embedding dim
#define HH    1024
#define AA    512     // attention dim
#define VV    20000
#define LL    25
#define TT    24      // decode steps = L-1

// ---------------- scratch (device global, no runtime alloc) ----------------
// offsets in floats
#define OFF_ATT_ENC  0u                         // 12544*512
#define OFF_EBIAS    6422528u                   // 1536*4096
#define OFF_WREC     12713984u                  // 1536*4096
#define OFF_WCAT     19005440u                  // 1024*1024
#define OFF_BCAT     20054016u                  // 1024
#define OFF_BREC     20055040u                  // 4096
#define OFF_MEAN     20059136u                  // 64*512
#define OFF_H        20091904u                  // 64*1024
#define OFF_C        20157440u                  // 64*1024
#define OFF_ATTDEC   20222976u                  // 64*1024
#define OFF_GC       20288512u                  // 64*512
#define OFF_GATES    20321280u                  // 64*4096
#define OFF_HALL     20583424u                  // 1536*1024
#define SCRATCH_TOTAL 22156288u

__device__ __align__(256) float g_scratch[SCRATCH_TOTAL];

// ---------------- prep: pack recurrent weight matrices ----------------
__global__ void prep_kernel(const float* __restrict__ Wdec, const float* __restrict__ Wfb,
                            const float* __restrict__ bdec, const float* __restrict__ bfb,
                            const float* __restrict__ Wih,  const float* __restrict__ Whh,
                            const float* __restrict__ bih,  const float* __restrict__ bhh)
{
    float* Wcat = g_scratch + OFF_WCAT;
    float* bcat = g_scratch + OFF_BCAT;
    float* Wrec = g_scratch + OFF_WREC;
    float* brec = g_scratch + OFF_BREC;

    int i = blockIdx.x * blockDim.x + threadIdx.x;
    int stride = gridDim.x * blockDim.x;

    // Wcat (1024 x 1024): [W_dec_att | W_fbeta]
    for (int idx = i; idx < 1024 * 1024; idx += stride) {
        int k = idx >> 10, c = idx & 1023;
        Wcat[idx] = (c < 512) ? Wdec[k * 512 + c] : Wfb[k * 512 + (c - 512)];
    }
    for (int idx = i; idx < 1024; idx += stride)
        bcat[idx] = (idx < 512) ? bdec[idx] : bfb[idx - 512];

    // Wrec (1536 x 4096): rows 0..511 = W_ih rows 1024..1535 (gated-context part),
    //                     rows 512..1535 = W_hh
    for (int idx = i; idx < 1536 * 4096; idx += stride) {
        int r = idx >> 12, c = idx & 4095;
        Wrec[idx] = (r < 512) ? Wih[(1024 + r) * 4096 + c] : Whh[(r - 512) * 4096 + c];
    }
    for (int idx = i; idx < 4096; idx += stride)
        brec[idx] = bih[idx] + bhh[idx];
}

// ---------------- mean over P ----------------
__global__ void mean_kernel(const float* __restrict__ enc)
{
    int b = blockIdx.x;
    float* mean = g_scratch + OFF_MEAN;
    for (int e = threadIdx.x; e < ENC; e += blockDim.x) {
        float s = 0.f;
        const float* base = enc + (size_t)(b * PP) * ENC + e;
        #pragma unroll 4
        for (int p = 0; p < PP; ++p) s += base[(size_t)p * ENC];
        mean[b * ENC + e] = s * (1.f / (float)PP);
    }
}

// ---------------- generic tf32 WMMA GEMM ----------------
// C[M,N] = A'[M,K] @ B[K,N] (+bias[N]) (+addend[(m0+r),n])
// AMODE 0: plain A1 (lda1);  1: concat A1(split cols, lda1) then A2 (lda2);
//       2: gather rows from A2=emb_table via caps (row m -> t=m>>6,b=m&63)
// CMODE 0: plain row-major C (ldc);  1: preds mapping row m=t*64+b -> out row b*24+t
#define GBM 64
#define GBN 64
#define GBK 16
#define APAD 4
#define BPAD 4

template<int AMODE, int CMODE>
__global__ __launch_bounds__(256)
void gemm_tf32(const float* __restrict__ A1, int lda1,
               const float* __restrict__ A2, int lda2, int asplit,
               const int*   __restrict__ caps,
               const float* __restrict__ Bm, int ldb,
               float* __restrict__ C, int ldc,
               const float* __restrict__ bias,
               const float* __restrict__ addend, int ldadd,
               int M, int N, int K)
{
    __shared__ float As[2][GBM][GBK + APAD];
    __shared__ float Bs[2][GBK][GBN + BPAD];
    __shared__ float Cs[GBM][GBN + BPAD];
    __shared__ int scap[GBM];

    const int n0 = blockIdx.x * GBN;
    const int m0 = blockIdx.y * GBM;
    const int tid = threadIdx.x;

    if (AMODE == 2) {
        if (tid < GBM) {
            int m = m0 + tid;
            int tt = m >> 6, bb = m & 63;
            scap[tid] = caps[bb * LL + tt];
        }
        __syncthreads();
    }

    const int am = tid >> 2;           // 0..63
    const int ak = (tid & 3) * 4;      // 0,4,8,12
    const int bk = tid >> 4;           // 0..15
    const int bn = (tid & 15) * 4;     // 0..60

    const int wid = tid >> 5;
    const int wr  = wid & 3;           // 4 warp-rows of 16
    const int wc  = wid >> 2;          // 2 warp-cols of 32

    wmma::fragment<wmma::accumulator, 16, 16, 8, float> c0, c1;
    wmma::fill_fragment(c0, 0.f);
    wmma::fill_fragment(c1, 0.f);

    const int nk = K / GBK;

    auto ldA = [&](int kt) -> float4 {
        int k = kt * GBK + ak;
        int m = m0 + am;
        const float* p;
        if (AMODE == 0)      p = A1 + (size_t)m * lda1 + k;
        else if (AMODE == 1) p = (k < asplit) ? (A1 + (size_t)m * lda1 + k)
                                              : (A2 + (size_t)m * lda2 + (k - asplit));
        else                 p = A2 + (size_t)scap[am] * lda2 + k;
        return *reinterpret_cast<const float4*>(p);
    };
    auto ldB = [&](int kt) -> float4 {
        int k = kt * GBK + bk;
        int n = n0 + bn;
        if (n < N) return *reinterpret_cast<const float4*>(Bm + (size_t)k * ldb + n);
        return make_float4(0.f, 0.f, 0.f, 0.f);
    };

    float4 ra = ldA(0);
    float4 rb = ldB(0);
    *reinterpret_cast<float4*>(&As[0][am][ak]) = ra;
    *reinterpret_cast<float4*>(&Bs[0][bk][bn]) = rb;
    __syncthreads();

    for (int kt = 0; kt < nk; ++kt) {
        int cur = kt & 1;
        if (kt + 1 < nk) { ra = ldA(kt + 1); rb = ldB(kt + 1); }

        #pragma unroll
        for (int kk = 0; kk < GBK; kk += 8) {
            wmma::fragment<wmma::matrix_a, 16, 16, 8, wmma::precision::tf32, wmma::row_major> af;
            wmma::fragment<wmma::matrix_b, 16, 16, 8, wmma::precision::tf32, wmma::row_major> bf0, bf1;
            wmma::load_matrix_sync(af, &As[cur][wr * 16][kk], GBK + APAD);
            #pragma unroll
            for (int i = 0; i < af.num_elements; ++i) af.x[i] = wmma::__float_to_tf32(af.x[i]);
            wmma::load_matrix_sync(bf0, &Bs[cur][kk][wc * 32], GBN + BPAD);
            wmma::load_matrix_sync(bf1, &Bs[cur][kk][wc * 32 + 16], GBN + BPAD);
            #pragma unroll
            for (int i = 0; i < bf0.num_elements; ++i) bf0.x[i] = wmma::__float_to_tf32(bf0.x[i]);
            #pragma unroll
            for (int i = 0; i < bf1.num_elements; ++i) bf1.x[i] = wmma::__float_to_tf32(bf1.x[i]);
            wmma::mma_sync(c0, af, bf0, c0);
            wmma::mma_sync(c1, af, bf1, c1);
        }

        if (kt + 1 < nk) {
            int nxt = cur ^ 1;
            *reinterpret_cast<float4*>(&As[nxt][am][ak]) = ra;
            *reinterpret_cast<float4*>(&Bs[nxt][bk][bn]) = rb;
        }
        __syncthreads();
    }

    wmma::store_matrix_sync(&Cs[wr * 16][wc * 32],      c0, GBN + BPAD, wmma::mem_row_major);
    wmma::store_matrix_sync(&Cs[wr * 16][wc * 32 + 16], c1, GBN + BPAD, wmma::mem_row_major);
    __syncthreads();

    #pragma unroll
    for (int i = 0; i < 16; ++i) {
        int idx = tid + i * 256;
        int r = idx >> 6, cn = idx & 63;
        int n = n0 + cn;
        if (n < N) {
            float v = Cs[r][cn];
            if (bias)   v += bias[n];
            if (addend) v += addend[(size_t)(m0 + r) * ldadd + n];
            if (CMODE == 0) {
                C[(size_t)(m0 + r) * ldc + n] = v;
            } else {
                int gr = m0 + r;
                int bb = gr & 63, tt = gr >> 6;
                C[((size_t)bb * TT + tt) * ldc + n] = v;
            }
        }
    }
}

// ---------------- attention: energy -> softmax -> context -> gated context ----------------
__global__ __launch_bounds__(256)
void attention_kernel(const float* __restrict__ enc,
                      const float* __restrict__ wfull,
                      const float* __restrict__ bfull,
                      float* __restrict__ alpha_out, int t)
{
    const int b = blockIdx.x;
    const int tid = threadIdx.x;
    const int wid = tid >> 5, lane = tid & 31;

    __shared__ float sa[AA];
    __shared__ float sw[AA];
    __shared__ float se[PP];
    __shared__ float sred[32];

    const float* attdec = g_scratch + OFF_ATTDEC;
    const float* att_enc = g_scratch + OFF_ATT_ENC;
    float* gc = g_scratch + OFF_GC;

    for (int i = tid; i < AA; i += 256) {
        sa[i] = attdec[b * 1024 + i];
        sw[i] = wfull[i];
    }
    __syncthreads();

    // energies
    for (int p = wid; p < PP; p += 8) {
        const float* row = att_enc + ((size_t)(b * PP + p)) * AA;
        float acc = 0.f;
        #pragma unroll
        for (int a = lane; a < AA; a += 32) {
            float x = row[a] + sa[a];
            x = x > 0.f ? x : 0.f;
            acc += x * sw[a];
        }
        #pragma unroll
        for (int o = 16; o; o >>= 1) acc += __shfl_xor_sync(0xffffffffu, acc, o);
        if (lane == 0) se[p] = acc + bfull[0];
    }
    __syncthreads();

    // softmax over P
    float v = (tid < PP) ? se[tid] : -1e30f;
    float m = v;
    #pragma unroll
    for (int o = 16; o; o >>= 1) m = fmaxf(m, __shfl_xor_sync(0xffffffffu, m, o));
    if (lane == 0) sred[wid] = m;
    __syncthreads();
    if (wid == 0) {
        float mm = (lane < 8) ? sred[lane] : -1e30f;
        #pragma unroll
        for (int o = 16; o; o >>= 1) mm = fmaxf(mm, __shfl_xor_sync(0xffffffffu, mm, o));
        if (lane == 0) sred[0] = mm;
    }
    __syncthreads();
    float mx = sred[0];
    __syncthreads();

    float ex = (tid < PP) ? expf(v - mx) : 0.f;
    float s = ex;
    #pragma unroll
    for (int o = 16; o; o >>= 1) s += __shfl_xor_sync(0xffffffffu, s, o);
    if (lane == 0) sred[wid] = s;
    __syncthreads();
    if (wid == 0) {
        float ss = (lane < 8) ? sred[lane] : 0.f;
        #pragma unroll
        for (int o = 16; o; o >>= 1) ss += __shfl_xor_sync(0xffffffffu, ss, o);
        if (lane == 0) sred[0] = ss;
    }
    __syncthreads();
    float inv = 1.f / sred[0];

    if (tid < PP) {
        float al = ex * inv;
        se[tid] = al;
        alpha_out[((size_t)b * TT + t) * PP + tid] = al;
    }
    __syncthreads();

    // context + fbeta gate
    for (int e = tid; e < ENC; e += 256) {
        const float* col = enc + (size_t)(b * PP) * ENC + e;
        float acc = 0.f;
        #pragma unroll 4
        for (int p = 0; p < PP; ++p) acc += se[p] * col[(size_t)p * ENC];
        float fb = attdec[b * 1024 + 512 + e];
        float gate = 1.f / (1.f + expf(-fb));
        gc[b * ENC + e] = gate * acc;
    }
}

// ---------------- LSTM pointwise ----------------
__global__ __launch_bounds__(256)
void lstm_kernel(int t)
{
    int idx = blockIdx.x * blockDim.x + threadIdx.x;   // 64*1024
    int b = idx >> 10, j = idx & 1023;

    const float* g = g_scratch + OFF_GATES + (size_t)b * 4096;
    float* cbuf = g_scratch + OFF_C;
    float* hbuf = g_scratch + OFF_H;
    float* hall = g_scratch + OFF_HALL;

    float gi = g[j], gf = g[j + 1024], gg = g[j + 2048], go = g[j + 3072];
    float c = cbuf[idx];
    float si = 1.f / (1.f + expf(-gi));
    float sf = 1.f / (1.f + expf(-gf));
    float so = 1.f / (1.f + expf(-go));
    float cn = sf * c + si * tanhf(gg);
    float h  = so * tanhf(cn);
    cbuf[idx] = cn;
    hbuf[idx] = h;
    hall[((size_t)t * BB + b) * 1024 + j] = h;
}

// ---------------- launch ----------------
extern "C" void kernel_launch(void* const* d_in, const int* in_sizes, int n_in,
                              void* d_out, int out_size)
{
    const float* enc       = (const float*)d_in[0];
    const int*   caps      = (const int*)  d_in[1];
    // d_in[2] = lengths (unused; T = 24)
    const float* W_enc_att = (const float*)d_in[3];
    const float* b_enc_att = (const float*)d_in[4];
    const float* W_dec_att = (const float*)d_in[5];
    const float* b_dec_att = (const float*)d_in[6];
    const float* W_full    = (const float*)d_in[7];
    const float* b_full    = (const float*)d_in[8];
    const float* emb       = (const float*)d_in[9];
    const float* W_ih      = (const float*)d_in[10];
    const float* b_ih      = (const float*)d_in[11];
    const float* W_hh      = (const float*)d_in[12];
    const float* b_hh      = (const float*)d_in[13];
    const float* W_init_h  = (const float*)d_in[14];
    const float* b_init_h  = (const float*)d_in[15];
    const float* W_init_c  = (const float*)d_in[16];
    const float* b_init_c  = (const float*)d_in[17];
    // W_fbeta/b_fbeta = d_in[18]/d_in[19]
    const float* W_fbeta   = (const float*)d_in[18];
    const float* b_fbeta   = (const float*)d_in[19];
    const float* W_fc      = (const float*)d_in[20];
    const float* b_fc      = (const float*)d_in[21];

    float* out = (float*)d_out;
    float* alpha_out = out + (size_t)BB * TT * VV;

    void* sp = nullptr;
    cudaGetSymbolAddress(&sp, g_scratch);
    float* S = (float*)sp;

    float* s_att_enc = S + OFF_ATT_ENC;
    float* s_ebias   = S + OFF_EBIAS;
    float* s_Wrec    = S + OFF_WREC;
    float* s_Wcat    = S + OFF_WCAT;
    float* s_bcat    = S + OFF_BCAT;
    float* s_brec    = S + OFF_BREC;
    float* s_mean    = S + OFF_MEAN;
    float* s_h       = S + OFF_H;
    float* s_c       = S + OFF_C;
    float* s_attdec  = S + OFF_ATTDEC;
    float* s_gc      = S + OFF_GC;
    float* s_gates   = S + OFF_GATES;
    float* s_hall    = S + OFF_HALL;

    // 1. pack recurrent weights + fused biases
    prep_kernel<<<1024, 256>>>(W_dec_att, W_fbeta, b_dec_att, b_fbeta, W_ih, W_hh, b_ih, b_hh);

    // 2. mean over P
    mean_kernel<<<BB, 256>>>(enc);

    // 3. h0 = mean @ W_init_h + b_init_h ; c0 likewise
    gemm_tf32<0,0><<<dim3(16, 1), 256>>>(s_mean, ENC, nullptr, 0, 0, nullptr,
                                         W_init_h, HH, s_h, HH, b_init_h, nullptr, 0,
                                         BB, HH, ENC);
    gemm_tf32<0,0><<<dim3(16, 1), 256>>>(s_mean, ENC, nullptr, 0, 0, nullptr,
                                         W_init_c, HH, s_c, HH, b_init_c, nullptr, 0,
                                         BB, HH, ENC);

    // 4. att_enc = enc @ W_enc_att + b_enc_att   (12544 x 512, K=512)
    gemm_tf32<0,0><<<dim3(8, 196), 256>>>(enc, ENC, nullptr, 0, 0, nullptr,
                                          W_enc_att, AA, s_att_enc, AA, b_enc_att, nullptr, 0,
                                          BB * PP, AA, ENC);

    // 5. ebias[t*64+b] = emb_table[captions[b][t]] @ W_ih[:1024] + (b_ih + b_hh)
    gemm_tf32<2,0><<<dim3(64, 24), 256>>>(nullptr, 0, emb, EE, 0, caps,
                                          W_ih, 4096, s_ebias, 4096, s_brec, nullptr, 0,
                                          TT * BB, 4096, EE);

    // 6. recurrence
    for (int t = 0; t < TT; ++t) {
        // att_dec | fbeta logits = h @ Wcat + bcat   (64 x 1024, K=1024)
        gemm_tf32<0,0><<<dim3(16, 1), 256>>>(s_h, HH, nullptr, 0, 0, nullptr,
                                             s_Wcat, 1024, s_attdec, 1024, s_bcat, nullptr, 0,
                                             BB, 1024, HH);
        // attention -> alpha (output) + gated context
        attention_kernel<<<BB, 256>>>(enc, W_full, b_full, alpha_out, t);
        // gates = [gc | h] @ Wrec + ebias[t]   (64 x 4096, K=1536)
        gemm_tf32<1,0><<<dim3(64, 1), 256>>>(s_gc, ENC, s_h, HH, ENC, nullptr,
                                             s_Wrec, 4096, s_gates, 4096, nullptr,
                                             s_ebias + (size_t)t * BB * 4096, 4096,
                                             BB, 4096, ENC + HH);
        // pointwise LSTM update, store h into h_all[t]
        lstm_kernel<<<256, 256>>>(t);
    }

    // 7. predictions = h_all @ W_fc + b_fc, written directly as (B, T, V)
    gemm_tf32<0,1><<<dim3((VV + GBN - 1) / GBN, TT), 256>>>(
        s_hall, HH, nullptr, 0, 0, nullptr,
        W_fc, VV, out, VV, b_fc, nullptr, 0,
        TT * BB, VV, HH);
}

// round 2
// speedup vs baseline: 1.3424x; 1.3424x over previous
#include <cuda_runtime.h>
#include <cuda_bf16.h>
#include <mma.h>
#include <math.h>

using namespace nvcuda;

// ---------------- problem constants ----------------
#define BB    64
#define PP    196
#define ENC   512
#define EE    1024
#define HH    1024
#define AA    512
#define VV    20000
#define LL    25
#define TT    24

// ---------------- scratch layout (floats) ----------------
#define OFF_ATT_ENC  0u            // 12544*512   = 6422528
#define OFF_EBIAS    6422528u      // 1536*4096   = 6291456
#define OFF_WREC     12713984u     // 1536*4096
#define OFF_WIH      19005440u     // 1024*4096
#define OFF_WCAT     23199744u     // 1024*1024
#define OFF_BCAT     24248320u     // 1024
#define OFF_BREC     24249344u     // 4096
#define OFF_MEAN     24253440u     // 64*512
#define OFF_SX       24286208u     // 2 * 64*1536 = 196608   ([gc | h], double buffered)
#define OFF_C        24482816u     // 64*1024
#define OFF_ATTDEC   24548352u     // 64*1024
#define OFF_HALL     24613888u     // 1536*1024
#define SCRATCH_TOTAL 26186752u

__device__ __align__(256) float g_scratch[SCRATCH_TOTAL];

// grid barrier state
__device__ unsigned g_bar_count = 0;
__device__ unsigned g_bar_gen   = 0;

// ---------------- prep: pack / permute weights ----------------
// Wcat (1024x1024) = [W_dec_att | W_fbeta], bcat
// Wrec_perm (1536x4096): rows 0..511 = W_ih rows 1024..1535, rows 512..1535 = W_hh;
//   columns permuted: col' = 4*j + q  (orig col = q*1024 + j)
// Wih_perm (1024x4096): W_ih rows 0..1023, same column permutation
// brec_perm (4096)
__global__ void prep_kernel(const float* __restrict__ Wdec, const float* __restrict__ Wfb,
                            const float* __restrict__ bdec, const float* __restrict__ bfb,
                            const float* __restrict__ Wih,  const float* __restrict__ Whh,
                            const float* __restrict__ bih,  const float* __restrict__ bhh)
{
    float* Wcat = g_scratch + OFF_WCAT;
    float* bcat = g_scratch + OFF_BCAT;
    float* Wrec = g_scratch + OFF_WREC;
    float* Wihp = g_scratch + OFF_WIH;
    float* brec = g_scratch + OFF_BREC;

    int i = blockIdx.x * blockDim.x + threadIdx.x;
    int stride = gridDim.x * blockDim.x;

    for (int idx = i; idx < 1024 * 1024; idx += stride) {
        int k = idx >> 10, c = idx & 1023;
        Wcat[idx] = (c < 512) ? Wdec[k * 512 + c] : Wfb[k * 512 + (c - 512)];
    }
    for (int idx = i; idx < 1024; idx += stride)
        bcat[idx] = (idx < 512) ? bdec[idx] : bfb[idx - 512];

    for (int idx = i; idx < 1536 * 4096; idx += stride) {
        int r = idx >> 12, cp = idx & 4095;
        int j = cp >> 2, q = cp & 3;
        int oc = q * 1024 + j;
        Wrec[idx] = (r < 512) ? Wih[(size_t)(1024 + r) * 4096 + oc]
                              : Whh[(size_t)(r - 512) * 4096 + oc];
    }
    for (int idx = i; idx < 1024 * 4096; idx += stride) {
        int r = idx >> 12, cp = idx & 4095;
        int j = cp >> 2, q = cp & 3;
        Wihp[idx] = Wih[(size_t)r * 4096 + q * 1024 + j];
    }
    for (int idx = i; idx < 4096; idx += stride) {
        int j = idx >> 2, q = idx & 3;
        brec[idx] = bih[q * 1024 + j] + bhh[q * 1024 + j];
    }
}

// ---------------- mean over P ----------------
__global__ void mean_kernel(const float* __restrict__ enc)
{
    int b = blockIdx.x;
    float* mean = g_scratch + OFF_MEAN;
    for (int e = threadIdx.x; e < ENC; e += blockDim.x) {
        float s = 0.f;
        const float* base = enc + (size_t)(b * PP) * ENC + e;
        #pragma unroll 4
        for (int p = 0; p < PP; ++p) s += base[(size_t)p * ENC];
        mean[b * ENC + e] = s * (1.f / (float)PP);
    }
}

// ================= big tf32 GEMM: 128x128 tile, 8 warps (32x64 each) =================
// AMODE 0: plain A (lda, row-clamped to M-1);  2: rows gathered from emb via caps
// CMODE 0: C[m][n];  1: preds remap m=t*64+b -> C[(b*24+t)][n]
template<int AMODE, int CMODE>
__global__ __launch_bounds__(256)
void big_gemm(const float* __restrict__ A, int lda,
              const float* __restrict__ emb, const int* __restrict__ caps,
              const float* __restrict__ B, int ldb,
              float* __restrict__ C, int ldc,
              const float* __restrict__ bias,
              int M, int N, int K)
{
    __shared__ float As[2][128][20];
    __shared__ float Bs[2][16][132];
    __shared__ int scap[128];

    const int tid = threadIdx.x;
    const int n0 = blockIdx.x * 128;
    const int m0 = blockIdx.y * 128;

    if (AMODE == 2) {
        if (tid < 128) {
            int m = m0 + tid;
            int tt = m >> 6, bb = m & 63;
            scap[tid] = caps[bb * LL + tt];
        }
        __syncthreads();
    }

    const int wid = tid >> 5;
    const int wr = wid & 3;            // 4 m-chunks of 32
    const int wc = wid >> 2;           // 2 n-chunks of 64

    // A loads: rows r0, r0+64 ; 4 cols of 4
    const int ar = tid >> 2, ac = (tid & 3) * 4;
    // B loads: rows br, br+8 ; cols bc..bc+3
    const int br = tid >> 5, bc = (tid & 31) * 4;

    const float* A0;
    const float* A1;
    if (AMODE == 0) {
        int r0 = m0 + ar;      if (r0 >= M) r0 = M - 1;
        int r1 = m0 + ar + 64; if (r1 >= M) r1 = M - 1;
        A0 = A + (size_t)r0 * lda + ac;
        A1 = A + (size_t)r1 * lda + ac;
    } else {
        A0 = emb + (size_t)scap[ar] * EE + ac;
        A1 = emb + (size_t)scap[ar + 64] * EE + ac;
    }
    const bool bv = (n0 + bc) < N;     // N % 4 == 0 -> full float4 valid
    const float* B0 = B + (size_t)br * ldb + n0 + bc;
    const float* B1 = B + (size_t)(br + 8) * ldb + n0 + bc;

    wmma::fragment<wmma::accumulator, 16, 16, 8, float> acc[2][4];
    #pragma unroll
    for (int i = 0; i < 2; ++i)
        #pragma unroll
        for (int j = 0; j < 4; ++j) wmma::fill_fragment(acc[i][j], 0.f);

    const int nk = K >> 4;

    float4 a0 = *(const float4*)(A0);
    float4 a1 = *(const float4*)(A1);
    float4 b0 = bv ? *(const float4*)(B0) : make_float4(0, 0, 0, 0);
    float4 b1 = bv ? *(const float4*)(B1) : make_float4(0, 0, 0, 0);
    *(float4*)&As[0][ar][ac]      = a0;
    *(float4*)&As[0][ar + 64][ac] = a1;
    *(float4*)&Bs[0][br][bc]      = b0;
    *(float4*)&Bs[0][br + 8][bc]  = b1;
    __syncthreads();

    for (int kt = 0; kt < nk; ++kt) {
        int buf = kt & 1;
        if (kt + 1 < nk) {
            int ko = (kt + 1) * 16;
            a0 = *(const float4*)(A0 + ko);
            a1 = *(const float4*)(A1 + ko);
            b0 = bv ? *(const float4*)(B0 + (size_t)ko * ldb) : make_float4(0, 0, 0, 0);
            b1 = bv ? *(const float4*)(B1 + (size_t)ko * ldb) : make_float4(0, 0, 0, 0);
        }
        #pragma unroll
        for (int ks = 0; ks < 2; ++ks) {
            wmma::fragment<wmma::matrix_a, 16, 16, 8, wmma::precision::tf32, wmma::row_major> af[2];
            wmma::fragment<wmma::matrix_b, 16, 16, 8, wmma::precision::tf32, wmma::row_major> bf[4];
            #pragma unroll
            for (int i = 0; i < 2; ++i) {
                wmma::load_matrix_sync(af[i], &As[buf][wr * 32 + i * 16][ks * 8], 20);
                #pragma unroll
                for (int e = 0; e < af[i].num_elements; ++e) af[i].x[e] = wmma::__float_to_tf32(af[i].x[e]);
            }
            #pragma unroll
            for (int j = 0; j < 4; ++j) {
                wmma::load_matrix_sync(bf[j], &Bs[buf][ks * 8][wc * 64 + j * 16], 132);
                #pragma unroll
                for (int e = 0; e < bf[j].num_elements; ++e) bf[j].x[e] = wmma::__float_to_tf32(bf[j].x[e]);
            }
            #pragma unroll
            for (int i = 0; i < 2; ++i)
                #pragma unroll
                for (int j = 0; j < 4; ++j)
                    wmma::mma_sync(acc[i][j], af[i], bf[j], acc[i][j]);
        }
        if (kt + 1 < nk) {
            int nb = buf ^ 1;
            *(float4*)&As[nb][ar][ac]      = a0;
            *(float4*)&As[nb][ar + 64][ac] = a1;
            *(float4*)&Bs[nb][br][bc]      = b0;
            *(float4*)&Bs[nb][br + 8][bc]  = b1;
        }
        __syncthreads();
    }

    // epilogue in 4 chunks of 32 rows, staged through smem (reuse As)
    float* Cs = &As[0][0][0];  // 32 x 132
    for (int chunk = 0; chunk < 4; ++chunk) {
        if (wr == chunk) {
            #pragma unroll
            for (int i = 0; i < 2; ++i)
                #pragma unroll
                for (int j = 0; j < 4; ++j)
                    wmma::store_matrix_sync(Cs + (i * 16) * 132 + wc * 64 + j * 16,
                                            acc[i][j], 132, wmma::mem_row_major);
        }
        __syncthreads();
        #pragma unroll
        for (int it = 0; it < 16; ++it) {
            int idx = tid + it * 256;
            int r = idx >> 7, cn = idx & 127;
            int m = m0 + chunk * 32 + r;
            int n = n0 + cn;
            if (m < M && n < N) {
                float v = Cs[r * 132 + cn] + bias[n];
                if (CMODE == 0) {
                    C[(size_t)m * ldc + n] = v;
                } else {
                    int bb = m & 63, tt = m >> 6;
                    C[((size_t)bb * TT + tt) * ldc + n] = v;
                }
            }
        }
        __syncthreads();
    }
}

// ================= persistent recurrence kernel =================
#define NBLK 128

__device__ __forceinline__ void grid_sync(unsigned& gen)
{
    __syncthreads();
    if (threadIdx.x == 0) {
        __threadfence();
        unsigned arrived = atomicAdd(&g_bar_count, 1u);
        if (arrived == (unsigned)(NBLK - 1)) {
            g_bar_count = 0;
            __threadfence();
            atomicAdd(&g_bar_gen, 1u);
        } else {
            while (*(volatile unsigned*)&g_bar_gen == gen) __nanosleep(64);
            __threadfence();
        }
    }
    gen++;
    __syncthreads();
}

// 64x32 output tile wmma gemm, GBK=32, double buffered. Result left in acc.
__device__ __forceinline__ void tile_gemm_64x32(
    const float* __restrict__ A, int lda,
    const float* __restrict__ B, int ldb, int K,
    float* sbuf,
    wmma::fragment<wmma::accumulator, 16, 16, 8, float>& acc)
{
    const int tid = threadIdx.x;
    const int wid = tid >> 5, wr = wid & 3, wc = wid >> 2;
    float* As = sbuf;           // [2][64][36] = 4608
    float* Bs = sbuf + 4608;    // [2][32][36] = 2304
    const int ar = tid >> 3, ac = (tid & 7) * 4;

    const float* Ap0 = A + (size_t)ar * lda + ac;
    const float* Ap1 = A + (size_t)(ar + 32) * lda + ac;
    const float* Bp  = B + (size_t)ar * ldb + ac;

    const int nk = K >> 5;
    float4 a0 = *(const float4*)(Ap0);
    float4 a1 = *(const float4*)(Ap1);
    float4 b0 = *(const float4*)(Bp);
    *(float4*)&As[ar * 36 + ac]        = a0;
    *(float4*)&As[(ar + 32) * 36 + ac] = a1;
    *(float4*)&Bs[ar * 36 + ac]        = b0;
    __syncthreads();

    for (int kt = 0; kt < nk; ++kt) {
        int buf = kt & 1;
        if (kt + 1 < nk) {
            int ko = (kt + 1) * 32;
            a0 = *(const float4*)(Ap0 + ko);
            a1 = *(const float4*)(Ap1 + ko);
            b0 = *(const float4*)(Bp + (size_t)ko * ldb);
        }
        const float* Ab = As + buf * 2304;
        const float* Bb = Bs + buf * 1152;
        #pragma unroll
        for (int kk = 0; kk < 4; ++kk) {
            wmma::fragment<wmma::matrix_a, 16, 16, 8, wmma::precision::tf32, wmma::row_major> af;
            wmma::fragment<wmma::matrix_b, 16, 16, 8, wmma::precision::tf32, wmma::row_major> bf;
            wmma::load_matrix_sync(af, Ab + (wr * 16) * 36 + kk * 8, 36);
            wmma::load_matrix_sync(bf, Bb + (kk * 8) * 36 + wc * 16, 36);
            #pragma unroll
            for (int e = 0; e < af.num_elements; ++e) af.x[e] = wmma::__float_to_tf32(af.x[e]);
            #pragma unroll
            for (int e = 0; e < bf.num_elements; ++e) bf.x[e] = wmma::__float_to_tf32(bf.x[e]);
            wmma::mma_sync(acc, af, bf, acc);
        }
        if (kt + 1 < nk) {
            int nb = buf ^ 1;
            *(float4*)&As[nb * 2304 + ar * 36 + ac]        = a0;
            *(float4*)&As[nb * 2304 + (ar + 32) * 36 + ac] = a1;
            *(float4*)&Bs[nb * 1152 + ar * 36 + ac]        = b0;
        }
        __syncthreads();
    }
}

__device__ __forceinline__ float sigm(float x) { return 1.f / (1.f + expf(-x)); }

__global__ __launch_bounds__(256, 1)
void recur_kernel(const float* __restrict__ enc,
                  const float* __restrict__ wfull,
                  const float* __restrict__ bfull,
                  float* __restrict__ alpha_out)
{
    __shared__ float sbuf[6912];

    const int bi = blockIdx.x;
    const int tid = threadIdx.x;
    const int wid = tid >> 5, lane = tid & 31;

    float* S = g_scratch;
    const float* att_enc = S + OFF_ATT_ENC;
    const float* Wcat    = S + OFF_WCAT;
    const float* bcat    = S + OFF_BCAT;
    const float* Wrec    = S + OFF_WREC;
    const float* ebias   = S + OFF_EBIAS;
    float* sx            = S + OFF_SX;        // [2][64][1536]
    float* cbuf          = S + OFF_C;
    float* attdec        = S + OFF_ATTDEC;
    float* hall          = S + OFF_HALL;

    unsigned gen = *(volatile unsigned*)&g_bar_gen;
    const float bf0 = bfull[0];

    for (int t = 0; t < TT; ++t) {
        const int cur = t & 1, nxt = cur ^ 1;
        float* sxc = sx + cur * (64 * 1536);
        float* sxn = sx + nxt * (64 * 1536);

        // ---- P1: attdec = h @ Wcat + bcat (blocks 0..31, 32-col tiles) ----
        if (bi < 32) {
            wmma::fragment<wmma::accumulator, 16, 16, 8, float> acc;
            wmma::fill_fragment(acc, 0.f);
            tile_gemm_64x32(sxc + 512, 1536, Wcat + bi * 32, 1024, HH, sbuf, acc);
            const int wr = wid & 3, wc = wid >> 2;
            wmma::store_matrix_sync(sbuf + (wr * 16) * 36 + wc * 16, acc, 36, wmma::mem_row_major);
            __syncthreads();
            const int n0 = bi * 32;
            #pragma unroll
            for (int i = 0; i < 8; ++i) {
                int idx = tid + i * 256;
                int r = idx >> 5, c = idx & 31;
                attdec[r * 1024 + n0 + c] = sbuf[r * 36 + c] + bcat[n0 + c];
            }
        }
        grid_sync(gen);

        // ---- P2: attention, one block per batch (blocks 0..63) ----
        if (bi < 64) {
            const int b = bi;
            float* sa = sbuf;
            float* sw = sbuf + 512;
            float* se = sbuf + 1024;
            float* sred = sbuf + 1224;

            for (int i = tid; i < AA; i += 256) {
                sa[i] = attdec[b * 1024 + i];
                sw[i] = wfull[i];
            }
            __syncthreads();

            for (int p = wid; p < PP; p += 8) {
                const float* row = att_enc + (size_t)(b * PP + p) * AA;
                float acc = 0.f;
                #pragma unroll 4
                for (int a = lane; a < AA; a += 32) {
                    float x = row[a] + sa[a];
                    x = x > 0.f ? x : 0.f;
                    acc += x * sw[a];
                }
                #pragma unroll
                for (int o = 16; o; o >>= 1) acc += __shfl_xor_sync(0xffffffffu, acc, o);
                if (lane == 0) se[p] = acc + bf0;
            }
            __syncthreads();

            float v = (tid < PP) ? se[tid] : -1e30f;
            float m = v;
            #pragma unroll
            for (int o = 16; o; o >>= 1) m = fmaxf(m, __shfl_xor_sync(0xffffffffu, m, o));
            if (lane == 0) sred[wid] = m;
            __syncthreads();
            if (wid == 0) {
                float mm = (lane < 8) ? sred[lane] : -1e30f;
                #pragma unroll
                for (int o = 16; o; o >>= 1) mm = fmaxf(mm, __shfl_xor_sync(0xffffffffu, mm, o));
                if (lane == 0) sred[0] = mm;
            }
            __syncthreads();
            float mx = sred[0];
            __syncthreads();

            float ex = (tid < PP) ? expf(v - mx) : 0.f;
            float s = ex;
            #pragma unroll
            for (int o = 16; o; o >>= 1) s += __shfl_xor_sync(0xffffffffu, s, o);
            if (lane == 0) sred[wid] = s;
            __syncthreads();
            if (wid == 0) {
                float ss = (lane < 8) ? sred[lane] : 0.f;
                #pragma unroll
                for (int o = 16; o; o >>= 1) ss += __shfl_xor_sync(0xffffffffu, ss, o);
                if (lane == 0) sred[0] = ss;
            }
            __syncthreads();
            float inv = 1.f / sred[0];

            if (tid < PP) {
                float al = ex * inv;
                se[tid] = al;
                alpha_out[((size_t)b * TT + t) * PP + tid] = al;
            }
            __syncthreads();

            for (int e = tid; e < ENC; e += 256) {
                const float* col = enc + (size_t)(b * PP) * ENC + e;
                float acc = 0.f;
                #pragma unroll 4
                for (int p = 0; p < PP; ++p) acc += se[p] * col[(size_t)p * ENC];
                float fb = attdec[b * 1024 + 512 + e];
                sxc[b * 1536 + e] = sigm(fb) * acc;
            }
        }
        grid_sync(gen);

        // ---- P3: gates = [gc|h] @ Wrec_perm + ebias_perm; fused LSTM (all 128 blocks) ----
        {
            wmma::fragment<wmma::accumulator, 16, 16, 8, float> acc;
            wmma::fill_fragment(acc, 0.f);
            const int n0 = bi * 32;
            tile_gemm_64x32(sxc, 1536, Wrec + n0, 4096, ENC + HH, sbuf, acc);
            const int wr = wid & 3, wc = wid >> 2;
            wmma::store_matrix_sync(sbuf + (wr * 16) * 36 + wc * 16, acc, 36, wmma::mem_row_major);
            __syncthreads();

            #pragma unroll
            for (int i = 0; i < 2; ++i) {
                int p = tid + i * 256;          // 0..511
                int b = p >> 3, jj = p & 7;
                int j = bi * 8 + jj;
                float4 g = *(float4*)&sbuf[b * 36 + jj * 4];
                float4 e = *(const float4*)&ebias[((size_t)t * BB + b) * 4096 + n0 + jj * 4];
                float gi = g.x + e.x, gf = g.y + e.y, gg = g.z + e.z, go = g.w + e.w;
                float co = cbuf[b * 1024 + j];
                float cn = sigm(gf) * co + sigm(gi) * tanhf(gg);
                float h  = sigm(go) * tanhf(cn);
                cbuf[b * 1024 + j] = cn;
                sxn[b * 1536 + 512 + j] = h;
                hall[((size_t)t * BB + b) * 1024 + j] = h;
            }
        }
        grid_sync(gen);
    }
}

// ---------------- launch ----------------
extern "C" void kernel_launch(void* const* d_in, const int* in_sizes, int n_in,
                              void* d_out, int out_size)
{
    const float* enc       = (const float*)d_in[0];
    const int*   caps      = (const int*)  d_in[1];
    const float* W_enc_att = (const float*)d_in[3];
    const float* b_enc_att = (const float*)d_in[4];
    const float* W_dec_att = (const float*)d_in[5];
    const float* b_dec_att = (const float*)d_in[6];
    const float* W_full    = (const float*)d_in[7];
    const float* b_full    = (const float*)d_in[8];
    const float* emb       = (const float*)d_in[9];
    const float* W_ih      = (const float*)d_in[10];
    const float* b_ih      = (const float*)d_in[11];
    const float* W_hh      = (const float*)d_in[12];
    const float* b_hh      = (const float*)d_in[13];
    const float* W_init_h  = (const float*)d_in[14];
    const float* b_init_h  = (const float*)d_in[15];
    const float* W_init_c  = (const float*)d_in[16];
    const float* b_init_c  = (const float*)d_in[17];
    const float* W_fbeta   = (const float*)d_in[18];
    const float* b_fbeta   = (const float*)d_in[19];
    const float* W_fc      = (const float*)d_in[20];
    const float* b_fc      = (const float*)d_in[21];

    float* out = (float*)d_out;
    float* alpha_out = out + (size_t)BB * TT * VV;

    void* sp = nullptr;
    cudaGetSymbolAddress(&sp, g_scratch);
    float* S = (float*)sp;

    // 1. pack/permute weights
    prep_kernel<<<1024, 256>>>(W_dec_att, W_fbeta, b_dec_att, b_fbeta, W_ih, W_hh, b_ih, b_hh);

    // 2. mean over P
    mean_kernel<<<BB, 256>>>(enc);

    // 3. h0 -> s_x[0] h-part (ldc 1536); c0 -> cbuf
    big_gemm<0, 0><<<dim3(8, 1), 256>>>(S + OFF_MEAN, ENC, nullptr, nullptr,
                                        W_init_h, HH, S + OFF_SX + 512, 1536,
                                        b_init_h, BB, HH, ENC);
    big_gemm<0, 0><<<dim3(8, 1), 256>>>(S + OFF_MEAN, ENC, nullptr, nullptr,
                                        W_init_c, HH, S + OFF_C, HH,
                                        b_init_c, BB, HH, ENC);

    // 4. att_enc = enc @ W_enc_att + b_enc_att
    big_gemm<0, 0><<<dim3(4, 98), 256>>>(enc, ENC, nullptr, nullptr,
                                         W_enc_att, AA, S + OFF_ATT_ENC, AA,
                                         b_enc_att, BB * PP, AA, ENC);

    // 5. ebias (permuted cols) = emb[caps] @ Wih_perm + brec_perm
    big_gemm<2, 0><<<dim3(32, 12), 256>>>(nullptr, 0, emb, caps,
                                          S + OFF_WIH, 4096, S + OFF_EBIAS, 4096,
                                          S + OFF_BREC, TT * BB, 4096, EE);

    // 6. persistent 24-step recurrence
    recur_kernel<<<NBLK, 256>>>(enc, W_full, b_full, alpha_out);

    // 7. predictions = h_all @ W_fc + b_fc (remapped to (B,T,V))
    big_gemm<0, 1><<<dim3(157, 12), 256>>>(S + OFF_HALL, HH, nullptr, nullptr,
                                           W_fc, VV, out, VV,
                                           b_fc, TT * BB, VV, HH);
}